// round 10
// baseline (speedup 1.0000x reference)
#include <cuda_runtime.h>
#include <cstdint>

#define HID  1024
#define ITR  4096
#define MTOT 16384

// Scratch: inter = ReLU(X@W1^T+b1) (pre-bumped), plus tf32-rna pre-rounded X/W1/W2.
__device__ float g_inter[(size_t)MTOT * (size_t)ITR];
__device__ float g_xb[(size_t)MTOT * (size_t)HID];
__device__ float g_w1b[(size_t)ITR * (size_t)HID];
__device__ float g_w2b[(size_t)HID * (size_t)ITR];

#if defined(__CUDA_ARCH_FEAT_SM103_ALL) || defined(__CUDA_ARCH_FEAT_SM100_ALL)
#define HAS_TC05 1
#else
#define HAS_TC05 0
#endif

// ---------------- smem layout (B tiles only; A goes through TMEM) ----------------
#define NSTAGE 4
#define BK 32                      // K per stage (4 x tf32 K=8 MMAs)
#define TILE_B 16384               // B stage: 128 rows x 128 B
#define SM_TMEM  0
#define SM_FULL  16                // [4] pair-full on leader (count 2)
#define SM_FLOC  48                // [4] local stage barrier (count 256: cp + sttm)
#define SM_EMPTY 80                // [4] stage free (commit multicast)
#define SM_DONE  112               // tile done (commit multicast)
#define SM_EPIF  120               // epilogue freed D (count 256, on leader)
#define SM_B 1024
#define SMEM_TOTAL (SM_B + NSTAGE * TILE_B)   // 66560 B

// TMEM columns: D tile 256 cols @0, A ring 4 x 32 cols @256
#define TM_D 0
#define TM_A 256

// idesc: c=F32(1)<<4 | a=TF32(2)<<7 | b=TF32(2)<<10 | (N/8=32)<<17 | (M/16=16)<<24
#define IDESC_TF32 0x10400910u
static constexpr uint64_t DESC_BASE =       // SW128 K-major: layout=2, ver=1, SBO=64, LBO=1
    (2ull << 61) | (1ull << 46) | (64ull << 32) | (1ull << 16);

// ---------------- common helpers ----------------
__device__ __forceinline__ uint32_t smem_u32(const void* p) {
    return (uint32_t)__cvta_generic_to_shared(p);
}
__device__ __forceinline__ void cp16(uint32_t d, const void* s) {
    asm volatile("cp.async.cg.shared.global [%0], [%1], 16;" :: "r"(d), "l"(s));
}
__device__ __forceinline__ void st_cs4(float* p, float a, float b, float c, float d) {
    asm volatile("st.global.cs.v4.f32 [%0], {%1,%2,%3,%4};"
                 :: "l"(p), "f"(a), "f"(b), "f"(c), "f"(d) : "memory");
}
// tf32 rna via half-ulp bump (HW truncates low 13 mantissa bits).
__device__ __forceinline__ float bumpf(float f) {
    return __uint_as_float(__float_as_uint(f) + 0x1000u);
}

// ---------------- prepass ----------------
__global__ void __launch_bounds__(256) bump_tf32_kernel(const float4* __restrict__ in,
                                                        float4* __restrict__ out, int n4) {
    int i = blockIdx.x * blockDim.x + threadIdx.x;
    if (i < n4) {
        float4 v = in[i];
        v.x = bumpf(v.x); v.y = bumpf(v.y); v.z = bumpf(v.z); v.w = bumpf(v.w);
        out[i] = v;
    }
}

#if HAS_TC05
// ---------------- tcgen05 helpers ----------------
__device__ __forceinline__ uint32_t ctarank() {
    uint32_t r; asm("mov.u32 %0, %%cluster_ctarank;" : "=r"(r)); return r;
}
__device__ __forceinline__ bool elect_one() {
    uint32_t p;
    asm volatile("{\n\t.reg .pred P;\n\telect.sync _|P, 0xFFFFFFFF;\n\tselp.b32 %0, 1, 0, P;\n\t}"
                 : "=r"(p));
    return p != 0;
}
__device__ __forceinline__ void mbar_init(uint32_t a, uint32_t cnt) {
    asm volatile("mbarrier.init.shared.b64 [%0], %1;" :: "r"(a), "r"(cnt) : "memory");
}
__device__ __forceinline__ void mbar_arrive_local(uint32_t a) {
    asm volatile("mbarrier.arrive.shared.b64 _, [%0];" :: "r"(a) : "memory");
}
__device__ __forceinline__ void mbar_arrive_cluster(uint32_t local_addr, uint32_t rank) {
    asm volatile("{\n\t.reg .b32 ra;\n\tmapa.shared::cluster.u32 ra, %0, %1;\n\t"
                 "mbarrier.arrive.shared::cluster.b64 _, [ra];\n\t}"
                 :: "r"(local_addr), "r"(rank) : "memory");
}
__device__ __forceinline__ void wait_parity(uint32_t a, uint32_t ph) {
    asm volatile("{\n\t.reg .pred P;\n"
                 "W_%=:\n\tmbarrier.try_wait.parity.acquire.cta.shared::cta.b64 P, [%0], %1, 0x989680;\n"
                 "\t@P bra D_%=;\n\tbra W_%=;\nD_%=:\n\t}"
                 :: "r"(a), "r"(ph) : "memory");
}
__device__ __forceinline__ void cp_arrive_noinc(uint32_t bar) {
    asm volatile("cp.async.mbarrier.arrive.noinc.shared::cta.b64 [%0];" :: "r"(bar) : "memory");
}
// TS form: A operand from TMEM, B from SMEM descriptor.
__device__ __forceinline__ void mma_cg2_tf32_ts(uint32_t d, uint32_t a, uint64_t bd,
                                                uint32_t idesc, uint32_t en) {
    asm volatile("{\n\t.reg .pred p;\n\tsetp.ne.u32 p, %4, 0;\n\t"
                 "tcgen05.mma.cta_group::2.kind::tf32 [%0], [%1], %2, %3, "
                 "{%5,%5,%5,%5,%5,%5,%5,%5}, p;\n\t}"
                 :: "r"(d), "r"(a), "l"(bd), "r"(idesc), "r"(en), "r"(0u) : "memory");
}
__device__ __forceinline__ void commit_mc(uint32_t bar) {
    asm volatile("tcgen05.commit.cta_group::2.mbarrier::arrive::one.shared::cluster.multicast::cluster.b64 [%0], %1;"
                 :: "r"(bar), "h"((uint16_t)3) : "memory");
}
__device__ __forceinline__ void tmem_alloc_cg2(uint32_t addr, uint32_t ncols) {
    asm volatile("tcgen05.alloc.cta_group::2.sync.aligned.shared::cta.b32 [%0], %1;"
                 :: "r"(addr), "r"(ncols) : "memory");
}
__device__ __forceinline__ void tmem_dealloc_cg2(uint32_t tmem, uint32_t ncols) {
    asm volatile("tcgen05.dealloc.cta_group::2.sync.aligned.b32 %0, %1;" :: "r"(tmem), "r"(ncols));
}
__device__ __forceinline__ void tmem_relinquish_cg2() {
    asm volatile("tcgen05.relinquish_alloc_permit.cta_group::2.sync.aligned;");
}
__device__ __forceinline__ void fence_after_sync() {
    asm volatile("tcgen05.fence::after_thread_sync;" ::: "memory");
}
__device__ __forceinline__ void fence_before_sync() {
    asm volatile("tcgen05.fence::before_thread_sync;" ::: "memory");
}
__device__ __forceinline__ void fence_proxy_async_cta() {
    asm volatile("fence.proxy.async.shared::cta;" ::: "memory");
}
__device__ __forceinline__ void cluster_sync() {
    asm volatile("barrier.cluster.arrive.aligned;" ::: "memory");
    asm volatile("barrier.cluster.wait.aligned;" ::: "memory");
}
__device__ __forceinline__ void wait_ld() {
    asm volatile("tcgen05.wait::ld.sync.aligned;" ::: "memory");
}
__device__ __forceinline__ void wait_st() {
    asm volatile("tcgen05.wait::st.sync.aligned;" ::: "memory");
}
#define LDTM_X32(r, taddr) \
    asm volatile( \
        "tcgen05.ld.sync.aligned.32x32b.x32.b32 " \
        "{%0, %1, %2, %3, %4, %5, %6, %7, " \
        " %8, %9, %10, %11, %12, %13, %14, %15, " \
        " %16, %17, %18, %19, %20, %21, %22, %23, " \
        " %24, %25, %26, %27, %28, %29, %30, %31}, [%32];" \
        : "=r"((r)[0]),  "=r"((r)[1]),  "=r"((r)[2]),  "=r"((r)[3]), \
          "=r"((r)[4]),  "=r"((r)[5]),  "=r"((r)[6]),  "=r"((r)[7]), \
          "=r"((r)[8]),  "=r"((r)[9]),  "=r"((r)[10]), "=r"((r)[11]), \
          "=r"((r)[12]), "=r"((r)[13]), "=r"((r)[14]), "=r"((r)[15]), \
          "=r"((r)[16]), "=r"((r)[17]), "=r"((r)[18]), "=r"((r)[19]), \
          "=r"((r)[20]), "=r"((r)[21]), "=r"((r)[22]), "=r"((r)[23]), \
          "=r"((r)[24]), "=r"((r)[25]), "=r"((r)[26]), "=r"((r)[27]), \
          "=r"((r)[28]), "=r"((r)[29]), "=r"((r)[30]), "=r"((r)[31]) \
        : "r"(taddr))
#define STTM_X32(taddr, r) \
    asm volatile( \
        "tcgen05.st.sync.aligned.32x32b.x32.b32 [%0], " \
        "{%1, %2, %3, %4, %5, %6, %7, %8, " \
        " %9, %10, %11, %12, %13, %14, %15, %16, " \
        " %17, %18, %19, %20, %21, %22, %23, %24, " \
        " %25, %26, %27, %28, %29, %30, %31, %32};" \
        :: "r"(taddr), \
           "r"((r)[0]),  "r"((r)[1]),  "r"((r)[2]),  "r"((r)[3]), \
           "r"((r)[4]),  "r"((r)[5]),  "r"((r)[6]),  "r"((r)[7]), \
           "r"((r)[8]),  "r"((r)[9]),  "r"((r)[10]), "r"((r)[11]), \
           "r"((r)[12]), "r"((r)[13]), "r"((r)[14]), "r"((r)[15]), \
           "r"((r)[16]), "r"((r)[17]), "r"((r)[18]), "r"((r)[19]), \
           "r"((r)[20]), "r"((r)[21]), "r"((r)[22]), "r"((r)[23]), \
           "r"((r)[24]), "r"((r)[25]), "r"((r)[26]), "r"((r)[27]), \
           "r"((r)[28]), "r"((r)[29]), "r"((r)[30]), "r"((r)[31]) \
        : "memory")
#else
__device__ __forceinline__ void mma_tf32(float* d, const uint32_t* a, const uint32_t* b) {
    asm volatile(
        "mma.sync.aligned.m16n8k8.row.col.f32.tf32.tf32.f32 "
        "{%0,%1,%2,%3}, {%4,%5,%6,%7}, {%8,%9}, {%0,%1,%2,%3};\n"
        : "+f"(d[0]), "+f"(d[1]), "+f"(d[2]), "+f"(d[3])
        : "r"(a[0]), "r"(a[1]), "r"(a[2]), "r"(a[3]), "r"(b[0]), "r"(b[1]));
}
#endif

// ---------------- kernel ----------------
// grid = (2, M/256), cluster (2,1,1), 288 threads, persistent over TPP N-tiles.
// Warps 0-3: produce B via cp.async AND A via LDG->tcgen05.st (TMEM ring).
// Warps 4-7: epilogue. Warp 8: TS-mode MMA issuer.
template <bool RELU>
__global__ void __launch_bounds__(288, 1) __cluster_dims__(2, 1, 1)
ffn_gemm(const float* __restrict__ A, const float* __restrict__ Bm,
         const float* __restrict__ bias, float* __restrict__ C,
         int K, int N, int TPP)
{
#if HAS_TC05
    extern __shared__ __align__(1024) char smem[];
    const uint32_t sb  = smem_u32(smem);
    const int tid = threadIdx.x;
    const int wid = tid >> 5;
    const uint32_t rank = ctarank();

    const int m0 = blockIdx.y * 256 + (int)rank * 128;
    const int KT = K / BK;

    if (wid == 8) {
        tmem_alloc_cg2(sb + SM_TMEM, 512);
        tmem_relinquish_cg2();
    }
    if (tid == 0) {
#pragma unroll
        for (int s = 0; s < NSTAGE; s++) {
            mbar_init(sb + SM_FULL  + s * 8, 2);
            mbar_init(sb + SM_FLOC  + s * 8, 256);   // 128 cp-arrives + 128 sttm-arrives
            mbar_init(sb + SM_EMPTY + s * 8, 1);
        }
        mbar_init(sb + SM_DONE, 1);
        mbar_init(sb + SM_EPIF, 256);
    }
    __syncthreads();
    uint32_t tmem;
    asm volatile("ld.shared.b32 %0, [%1];" : "=r"(tmem) : "r"(sb + SM_TMEM));
    cluster_sync();

    if (wid < 4) {
        // ======== producers: B -> smem (cp.async), A -> TMEM (LDG + sttm) ========
        uint32_t swoff[8]; int rowc[8], colc[8];
#pragma unroll
        for (int i = 0; i < 8; i++) {
            int chunk = tid + i * 128;              // 0..1023: row=chunk/8, 16B col=chunk%8
            rowc[i] = chunk >> 3; colc[i] = chunk & 7;
            uint32_t off = (uint32_t)(rowc[i] * 128 + colc[i] * 16);
            swoff[i] = off ^ ((off >> 3) & 0x70);
        }
        const float* Arow = A + (size_t)(m0 + tid) * K;   // one M-row per producer
        const uint32_t aw_base = tmem + TM_A + ((uint32_t)(tid >> 5) << 21);
        float4 ar[8];                                     // 32 K-floats, one k-tile
#pragma unroll
        for (int q = 0; q < 8; q++) ar[q] = ((const float4*)Arow)[q];   // kt=0

        int es = 0; uint32_t ep = 1;
        for (int t = 0; t < TPP; t++) {
            const int n0 = t * 256 + (int)rank * 128;
            for (int kt = 0; kt < KT; kt++) {
                wait_parity(sb + SM_EMPTY + es * 8, ep);
                // B tile via cp.async
                const uint32_t sbt = sb + SM_B + es * TILE_B;
                const int kb = kt * BK;
#pragma unroll
                for (int i = 0; i < 8; i++)
                    cp16(sbt + swoff[i], Bm + (size_t)(n0 + rowc[i]) * K + kb + colc[i] * 4);
                cp_arrive_noinc(sb + SM_FLOC + es * 8);
                // A k-tile (prefetched regs) -> TMEM ring
                STTM_X32(aw_base + es * 32, ((const uint32_t*)ar));
                wait_st();
                fence_before_sync();
                mbar_arrive_local(sb + SM_FLOC + es * 8);
                // prefetch next A k-tile
                const int nkb = (kt + 1 == KT) ? 0 : kb + BK;
#pragma unroll
                for (int q = 0; q < 8; q++)
                    ar[q] = ((const float4*)(Arow + nkb))[q];
                if (++es == NSTAGE) { es = 0; ep ^= 1; }
            }
        }
    } else if (wid == 8) {
        // ======== MMA issuer / notifier ========
        if (elect_one()) {
            int ls = 0; uint32_t lp = 0;
            int fs = 0; uint32_t fp = 0;
            uint32_t efp = 1;
            for (int t = 0; t < TPP; t++) {
                for (int kt = 0; kt < KT; kt++) {
                    wait_parity(sb + SM_FLOC + ls * 8, lp);
                    fence_proxy_async_cta();
                    mbar_arrive_cluster(sb + SM_FULL + ls * 8, 0);
                    if (rank == 0) {
                        if (kt == 0) {                    // D drained by epilogue?
                            wait_parity(sb + SM_EPIF, efp);
                            efp ^= 1;
                        }
                        wait_parity(sb + SM_FULL + fs * 8, fp);
                        fence_after_sync();
                        const uint64_t bd = DESC_BASE | (((sb + SM_B + fs * TILE_B) >> 4) & 0x3FFF);
                        const uint32_t at = tmem + TM_A + fs * 32;
#pragma unroll
                        for (int ks = 0; ks < 4; ks++)    // 4 x K=8 tf32 TS MMAs
                            mma_cg2_tf32_ts(tmem + TM_D, at + ks * 8, bd + ks * 2,
                                            IDESC_TF32, (kt > 0 || ks > 0) ? 1u : 0u);
                        commit_mc(sb + SM_EMPTY + fs * 8);
                        if (kt == KT - 1)
                            commit_mc(sb + SM_DONE);
                        if (++fs == NSTAGE) { fs = 0; fp ^= 1; }
                    }
                    if (++ls == NSTAGE) { ls = 0; lp ^= 1; }
                }
            }
        }
    } else {
        // ======== epilogue: warps 4-7, one TMEM subpartition each ========
        const int sub  = wid - 4;
        const int lane = tid & 31;
        const int grow = m0 + sub * 32 + lane;
        float* crow = C + (size_t)grow * N;
        uint32_t dnp = 0;
        for (int t = 0; t < TPP; t++) {
            wait_parity(sb + SM_DONE, dnp);
            dnp ^= 1;
            fence_after_sync();
#pragma unroll
            for (int c4 = 0; c4 < 8; c4++) {
                uint32_t r[32];
                LDTM_X32(r, tmem + TM_D + c4 * 32);
                wait_ld();
                const int gc0 = t * 256 + c4 * 32;
#pragma unroll
                for (int j = 0; j < 32; j += 4) {
                    float4 bv = *(const float4*)(bias + gc0 + j);
                    float v0 = __uint_as_float(r[j])     + bv.x;
                    float v1 = __uint_as_float(r[j + 1]) + bv.y;
                    float v2 = __uint_as_float(r[j + 2]) + bv.z;
                    float v3 = __uint_as_float(r[j + 3]) + bv.w;
                    if (RELU) {
                        v0 = bumpf(fmaxf(v0, 0.f)); v1 = bumpf(fmaxf(v1, 0.f));
                        v2 = bumpf(fmaxf(v2, 0.f)); v3 = bumpf(fmaxf(v3, 0.f));
                    }
                    st_cs4(crow + gc0 + j, v0, v1, v2, v3);
                }
            }
            fence_before_sync();
            mbar_arrive_cluster(sb + SM_EPIF, 0);   // release D
        }
    }

    __syncthreads();
    if (wid == 8) tmem_dealloc_cg2(tmem, 512);
    cluster_sync();
#else
    // ================= fallback: legacy mma.sync tf32 (generic PTX pass) ========
    extern __shared__ float sm[];
    const int tid  = threadIdx.x;
    const int lane = tid & 31;
    const int wid  = tid >> 5;
    const int m0 = blockIdx.y * 256 + blockIdx.x * 128;
    const int KT2 = K / 32;
    const int AT = 128 * 36;
    const int BT = 256 * 36;
    const uint32_t s0 = smem_u32(sm);

    for (int t = 0; t < TPP; t++) {
        const int nb = t * 256;
        float acc[4][8][4];
        if (tid < 256) {
#pragma unroll
            for (int i = 0; i < 4; i++)
#pragma unroll
                for (int j = 0; j < 8; j++)
#pragma unroll
                    for (int c = 0; c < 4; c++) acc[i][j][c] = 0.f;
        }
        auto load_tile = [&](int kt, int st) {
            if (tid < 256) {
                const float* Ag = A  + (size_t)m0 * K + (size_t)kt * 32;
                const float* Bg = Bm + (size_t)nb * K + (size_t)kt * 32;
                const uint32_t sA = s0 + (uint32_t)(st * (AT + BT)) * 4;
                const uint32_t sB = sA + (uint32_t)AT * 4;
#pragma unroll
                for (int q = 0; q < 4; q++) {
                    int ch = tid + q * 256; int row = ch >> 3, c4 = ch & 7;
                    cp16(sA + (uint32_t)(row * 36 + c4 * 4) * 4, Ag + (size_t)row * K + c4 * 4);
                }
#pragma unroll
                for (int q = 0; q < 8; q++) {
                    int ch = tid + q * 256; int row = ch >> 3, c4 = ch & 7;
                    cp16(sB + (uint32_t)(row * 36 + c4 * 4) * 4, Bg + (size_t)row * K + c4 * 4);
                }
            }
            asm volatile("cp.async.commit_group;");
        };
        load_tile(0, 0);
        for (int kt = 0; kt < KT2; kt++) {
            const int st = kt & 1;
            if (kt + 1 < KT2) { load_tile(kt + 1, st ^ 1);
                                asm volatile("cp.async.wait_group 1;"); }
            else              { asm volatile("cp.async.wait_group 0;"); }
            __syncthreads();
            if (tid < 256) {
                const float* As = sm + st * (AT + BT);
                const float* Bs = As + AT;
                const int wm = wid >> 2, wn = wid & 3;
                const int g = lane >> 2, tg = lane & 3;
#pragma unroll
                for (int ks = 0; ks < 4; ks++) {
                    const int k0 = ks * 8;
                    uint32_t af[4][4], bf[8][2];
#pragma unroll
                    for (int i = 0; i < 4; i++) {
                        const int r = wm * 64 + i * 16 + g;
                        af[i][0] = __float_as_uint(As[(r    ) * 36 + k0 + tg    ]);
                        af[i][1] = __float_as_uint(As[(r + 8) * 36 + k0 + tg    ]);
                        af[i][2] = __float_as_uint(As[(r    ) * 36 + k0 + tg + 4]);
                        af[i][3] = __float_as_uint(As[(r + 8) * 36 + k0 + tg + 4]);
                    }
#pragma unroll
                    for (int j = 0; j < 8; j++) {
                        const int c = wn * 64 + j * 8 + g;
                        bf[j][0] = __float_as_uint(Bs[c * 36 + k0 + tg    ]);
                        bf[j][1] = __float_as_uint(Bs[c * 36 + k0 + tg + 4]);
                    }
#pragma unroll
                    for (int i = 0; i < 4; i++)
#pragma unroll
                        for (int j = 0; j < 8; j++)
                            mma_tf32(acc[i][j], af[i], bf[j]);
                }
            }
            __syncthreads();
        }
        if (tid < 256) {
            const int wm = wid >> 2, wn = wid & 3;
            const int g = lane >> 2, tg = lane & 3;
#pragma unroll
            for (int i = 0; i < 4; i++) {
                const int r0 = m0 + wm * 64 + i * 16 + g;
#pragma unroll
                for (int j = 0; j < 8; j++) {
                    const int c = nb + wn * 64 + j * 8 + tg * 2;
                    const float bv0 = bias[c], bv1 = bias[c + 1];
                    float v0 = acc[i][j][0] + bv0, v1 = acc[i][j][1] + bv1;
                    float v2 = acc[i][j][2] + bv0, v3 = acc[i][j][3] + bv1;
                    if (RELU) {
                        v0 = bumpf(fmaxf(v0, 0.f)); v1 = bumpf(fmaxf(v1, 0.f));
                        v2 = bumpf(fmaxf(v2, 0.f)); v3 = bumpf(fmaxf(v3, 0.f));
                    }
                    *(float2*)(C + (size_t)r0 * N + c)       = make_float2(v0, v1);
                    *(float2*)(C + (size_t)(r0 + 8) * N + c) = make_float2(v2, v3);
                }
            }
        }
        __syncthreads();
    }
#endif
}

// ---------------- launch ----------------
extern "C" void kernel_launch(void* const* d_in, const int* in_sizes, int n_in,
                              void* d_out, int out_size) {
    (void)in_sizes; (void)n_in; (void)out_size;
    const float* x  = (const float*)d_in[0];
    const float* W1 = (const float*)d_in[1];
    const float* b1 = (const float*)d_in[2];
    const float* W2 = (const float*)d_in[3];
    const float* b2 = (const float*)d_in[4];
    float* out = (float*)d_out;

    float *inter, *xb, *w1b, *w2b;
    cudaGetSymbolAddress((void**)&inter, g_inter);
    cudaGetSymbolAddress((void**)&xb,  g_xb);
    cudaGetSymbolAddress((void**)&w1b, g_w1b);
    cudaGetSymbolAddress((void**)&w2b, g_w2b);

    cudaFuncSetAttribute(ffn_gemm<true>,
                         cudaFuncAttributeMaxDynamicSharedMemorySize, SMEM_TOTAL);
    cudaFuncSetAttribute(ffn_gemm<false>,
                         cudaFuncAttributeMaxDynamicSharedMemorySize, SMEM_TOTAL);

    // Prepass: tf32-rna pre-round of X, W1, W2 (inter pre-rounded in epilogue).
    {
        int n4;
        n4 = MTOT * HID / 4;
        bump_tf32_kernel<<<(n4 + 255) / 256, 256>>>((const float4*)x,  (float4*)xb,  n4);
        n4 = ITR * HID / 4;
        bump_tf32_kernel<<<(n4 + 255) / 256, 256>>>((const float4*)W1, (float4*)w1b, n4);
        n4 = HID * ITR / 4;
        bump_tf32_kernel<<<(n4 + 255) / 256, 256>>>((const float4*)W2, (float4*)w2b, n4);
    }

    // GEMM1: inter = bump(ReLU(X @ W1^T + b1))  [16384,4096], K=1024
    ffn_gemm<true><<<dim3(2, MTOT / 256, 1), 288, SMEM_TOTAL>>>(
        xb, w1b, b1, inter, HID, ITR, ITR / 256);

    // GEMM2: out = inter @ W2^T + b2            [16384,1024], K=4096
    ffn_gemm<false><<<dim3(2, MTOT / 256, 1), 288, SMEM_TOTAL>>>(
        inter, w2b, b2, out, ITR, HID, HID / 256);
}

// round 12
// speedup vs baseline: 3.3759x; 3.3759x over previous
#include <cuda_runtime.h>
#include <cuda_fp16.h>
#include <cstdint>

#define HID  1024
#define ITR  4096
#define MTOT 16384

// Scratch: fp16 copies of X/W1/W2 and the fp16 intermediate ReLU(X@W1^T+b1).
__device__ __half g_inter[(size_t)MTOT * (size_t)ITR];
__device__ __half g_xh[(size_t)MTOT * (size_t)HID];
__device__ __half g_w1h[(size_t)ITR * (size_t)HID];
__device__ __half g_w2h[(size_t)HID * (size_t)ITR];

#if defined(__CUDA_ARCH_FEAT_SM103_ALL) || defined(__CUDA_ARCH_FEAT_SM100_ALL)
#define HAS_TC05 1
#else
#define HAS_TC05 0
#endif

// ---------------- smem layout ----------------
#define NSTAGE 6
#define BK 64                      // K (fp16) per stage: 4 x K=16 f16 MMAs
#define TILE_B 16384               // 128 rows x 128 B per operand stage
#define SM_TMEM  0
#define SM_FULL  16                // [6] pair-full on leader (count 2)
#define SM_FLOC  64                // [6] local cp.async barrier (count 128)
#define SM_EMPTY 112               // [6] stage free (commit multicast)
#define SM_DONE  160               // [2] tile done per D buffer (commit multicast)
#define SM_EPIF  176               // [2] epilogue freed D buffer (count 256, on leader)
#define SM_A 1024
#define SM_B (SM_A + NSTAGE * TILE_B)
#define SMEM_TOTAL (SM_B + NSTAGE * TILE_B)   // 197632 B

// idesc kind::f16, fp16 inputs: c=F32(1)<<4 | a=FP16(0)<<7 | b=FP16(0)<<10
//                               | (N/8=32)<<17 | (M/16=16)<<24
#define IDESC_F16 0x10400010u
static constexpr uint64_t DESC_BASE =       // SW128 K-major: layout=2, ver=1, SBO=64, LBO=1
    (2ull << 61) | (1ull << 46) | (64ull << 32) | (1ull << 16);

// ---------------- common helpers ----------------
__device__ __forceinline__ uint32_t smem_u32(const void* p) {
    return (uint32_t)__cvta_generic_to_shared(p);
}
__device__ __forceinline__ void cp16(uint32_t d, const void* s) {
    asm volatile("cp.async.cg.shared.global [%0], [%1], 16;" :: "r"(d), "l"(s));
}
__device__ __forceinline__ void st_cs4(float* p, float a, float b, float c, float d) {
    asm volatile("st.global.cs.v4.f32 [%0], {%1,%2,%3,%4};"
                 :: "l"(p), "f"(a), "f"(b), "f"(c), "f"(d) : "memory");
}
__device__ __forceinline__ void st_cs_h4(__half* p, uint32_t h01, uint32_t h23) {
    asm volatile("st.global.cs.v2.b32 [%0], {%1,%2};"
                 :: "l"(p), "r"(h01), "r"(h23) : "memory");
}

// ---------------- prepass: f32 -> f16 (rn) ----------------
// Each thread: 8 elements (two float4 in, one uint4=8 halves out).
__global__ void __launch_bounds__(256) cvt_f16_kernel(const float4* __restrict__ in,
                                                      uint4* __restrict__ out, int n8) {
    int i = blockIdx.x * blockDim.x + threadIdx.x;
    if (i < n8) {
        float4 a = in[2 * i], b = in[2 * i + 1];
        __half2 h0 = __floats2half2_rn(a.x, a.y);
        __half2 h1 = __floats2half2_rn(a.z, a.w);
        __half2 h2 = __floats2half2_rn(b.x, b.y);
        __half2 h3 = __floats2half2_rn(b.z, b.w);
        uint4 o;
        o.x = *(uint32_t*)&h0; o.y = *(uint32_t*)&h1;
        o.z = *(uint32_t*)&h2; o.w = *(uint32_t*)&h3;
        out[i] = o;
    }
}

#if HAS_TC05
// ---------------- tcgen05 helpers ----------------
__device__ __forceinline__ uint32_t ctarank() {
    uint32_t r; asm("mov.u32 %0, %%cluster_ctarank;" : "=r"(r)); return r;
}
__device__ __forceinline__ bool elect_one() {
    uint32_t p;
    asm volatile("{\n\t.reg .pred P;\n\telect.sync _|P, 0xFFFFFFFF;\n\tselp.b32 %0, 1, 0, P;\n\t}"
                 : "=r"(p));
    return p != 0;
}
__device__ __forceinline__ void mbar_init(uint32_t a, uint32_t cnt) {
    asm volatile("mbarrier.init.shared.b64 [%0], %1;" :: "r"(a), "r"(cnt) : "memory");
}
__device__ __forceinline__ void mbar_arrive_cluster(uint32_t local_addr, uint32_t rank) {
    asm volatile("{\n\t.reg .b32 ra;\n\tmapa.shared::cluster.u32 ra, %0, %1;\n\t"
                 "mbarrier.arrive.shared::cluster.b64 _, [ra];\n\t}"
                 :: "r"(local_addr), "r"(rank) : "memory");
}
__device__ __forceinline__ void wait_parity(uint32_t a, uint32_t ph) {
    asm volatile("{\n\t.reg .pred P;\n"
                 "W_%=:\n\tmbarrier.try_wait.parity.acquire.cta.shared::cta.b64 P, [%0], %1, 0x989680;\n"
                 "\t@P bra D_%=;\n\tbra W_%=;\nD_%=:\n\t}"
                 :: "r"(a), "r"(ph) : "memory");
}
__device__ __forceinline__ void cp_arrive_noinc(uint32_t bar) {
    asm volatile("cp.async.mbarrier.arrive.noinc.shared::cta.b64 [%0];" :: "r"(bar) : "memory");
}
__device__ __forceinline__ void mma_cg2_f16(uint32_t d, uint64_t ad, uint64_t bd,
                                            uint32_t idesc, uint32_t en) {
    asm volatile("{\n\t.reg .pred p;\n\tsetp.ne.u32 p, %4, 0;\n\t"
                 "tcgen05.mma.cta_group::2.kind::f16 [%0], %1, %2, %3, "
                 "{%5,%5,%5,%5,%5,%5,%5,%5}, p;\n\t}"
                 :: "r"(d), "l"(ad), "l"(bd), "r"(idesc), "r"(en), "r"(0u) : "memory");
}
__device__ __forceinline__ void commit_mc(uint32_t bar) {
    asm volatile("tcgen05.commit.cta_group::2.mbarrier::arrive::one.shared::cluster.multicast::cluster.b64 [%0], %1;"
                 :: "r"(bar), "h"((uint16_t)3) : "memory");
}
__device__ __forceinline__ void tmem_alloc_cg2(uint32_t addr, uint32_t ncols) {
    asm volatile("tcgen05.alloc.cta_group::2.sync.aligned.shared::cta.b32 [%0], %1;"
                 :: "r"(addr), "r"(ncols) : "memory");
}
__device__ __forceinline__ void tmem_dealloc_cg2(uint32_t tmem, uint32_t ncols) {
    asm volatile("tcgen05.dealloc.cta_group::2.sync.aligned.b32 %0, %1;" :: "r"(tmem), "r"(ncols));
}
__device__ __forceinline__ void tmem_relinquish_cg2() {
    asm volatile("tcgen05.relinquish_alloc_permit.cta_group::2.sync.aligned;");
}
__device__ __forceinline__ void fence_after_sync() {
    asm volatile("tcgen05.fence::after_thread_sync;" ::: "memory");
}
__device__ __forceinline__ void fence_before_sync() {
    asm volatile("tcgen05.fence::before_thread_sync;" ::: "memory");
}
__device__ __forceinline__ void fence_proxy_async_cta() {
    asm volatile("fence.proxy.async.shared::cta;" ::: "memory");
}
__device__ __forceinline__ void cluster_sync() {
    asm volatile("barrier.cluster.arrive.aligned;" ::: "memory");
    asm volatile("barrier.cluster.wait.aligned;" ::: "memory");
}
__device__ __forceinline__ void wait_ld() {
    asm volatile("tcgen05.wait::ld.sync.aligned;" ::: "memory");
}
#define LDTM_X32(r, taddr) \
    asm volatile( \
        "tcgen05.ld.sync.aligned.32x32b.x32.b32 " \
        "{%0, %1, %2, %3, %4, %5, %6, %7, " \
        " %8, %9, %10, %11, %12, %13, %14, %15, " \
        " %16, %17, %18, %19, %20, %21, %22, %23, " \
        " %24, %25, %26, %27, %28, %29, %30, %31}, [%32];" \
        : "=r"((r)[0]),  "=r"((r)[1]),  "=r"((r)[2]),  "=r"((r)[3]), \
          "=r"((r)[4]),  "=r"((r)[5]),  "=r"((r)[6]),  "=r"((r)[7]), \
          "=r"((r)[8]),  "=r"((r)[9]),  "=r"((r)[10]), "=r"((r)[11]), \
          "=r"((r)[12]), "=r"((r)[13]), "=r"((r)[14]), "=r"((r)[15]), \
          "=r"((r)[16]), "=r"((r)[17]), "=r"((r)[18]), "=r"((r)[19]), \
          "=r"((r)[20]), "=r"((r)[21]), "=r"((r)[22]), "=r"((r)[23]), \
          "=r"((r)[24]), "=r"((r)[25]), "=r"((r)[26]), "=r"((r)[27]), \
          "=r"((r)[28]), "=r"((r)[29]), "=r"((r)[30]), "=r"((r)[31]) \
        : "r"(taddr))
#else
// Fallback uses legacy mma.sync fp16.
__device__ __forceinline__ void mma_f16(float* d, const uint32_t* a, const uint32_t* b) {
    asm volatile(
        "mma.sync.aligned.m16n8k16.row.col.f32.f16.f16.f32 "
        "{%0,%1,%2,%3}, {%4,%5,%6,%7}, {%8,%9}, {%0,%1,%2,%3};\n"
        : "+f"(d[0]), "+f"(d[1]), "+f"(d[2]), "+f"(d[3])
        : "r"(a[0]), "r"(a[1]), "r"(a[2]), "r"(a[3]), "r"(b[0]), "r"(b[1]));
}
#endif

// ---------------- kernel ----------------
// grid = (2, M/256), cluster (2,1,1), 288 threads, persistent over TPP N-tiles.
// Warps 0-3 produce (cp.async fp16 tiles), warps 4-7 epilogue, warp 8 MMA.
// RELU=true: C is __half* (fp16 inter). RELU=false: C is float* (final out).
template <bool RELU>
__global__ void __launch_bounds__(288, 1) __cluster_dims__(2, 1, 1)
ffn_gemm(const __half* __restrict__ A, const __half* __restrict__ Bm,
         const float* __restrict__ bias, void* __restrict__ Cv,
         int K, int N, int TPP)
{
#if HAS_TC05
    extern __shared__ __align__(1024) char smem[];
    const uint32_t sb  = smem_u32(smem);
    const int tid = threadIdx.x;
    const int wid = tid >> 5;
    const uint32_t rank = ctarank();

    const int m0 = blockIdx.y * 256 + (int)rank * 128;
    const int KT = K / BK;

    if (wid == 8) {
        tmem_alloc_cg2(sb + SM_TMEM, 512);
        tmem_relinquish_cg2();
    }
    if (tid == 0) {
#pragma unroll
        for (int s = 0; s < NSTAGE; s++) {
            mbar_init(sb + SM_FULL  + s * 8, 2);
            mbar_init(sb + SM_FLOC  + s * 8, 128);
            mbar_init(sb + SM_EMPTY + s * 8, 1);
        }
        mbar_init(sb + SM_DONE,      1);
        mbar_init(sb + SM_DONE + 8,  1);
        mbar_init(sb + SM_EPIF,      256);
        mbar_init(sb + SM_EPIF + 8,  256);
    }
    __syncthreads();
    uint32_t tmem;
    asm volatile("ld.shared.b32 %0, [%1];" : "=r"(tmem) : "r"(sb + SM_TMEM));
    cluster_sync();

    if (wid < 4) {
        // ======== producers: 128 threads, 16 cp16 per stage (A+B) ========
        // stage row = 64 fp16 = 128 B; chunk = 16 B = 8 halves.
        uint32_t swoff[8]; int rowc[8], colc[8];
#pragma unroll
        for (int i = 0; i < 8; i++) {
            int chunk = tid + i * 128;              // 0..1023
            rowc[i] = chunk >> 3; colc[i] = chunk & 7;
            uint32_t off = (uint32_t)(rowc[i] * 128 + colc[i] * 16);
            swoff[i] = off ^ ((off >> 3) & 0x70);
        }
        int es = 0; uint32_t ep = 1;
        for (int t = 0; t < TPP; t++) {
            const int n0 = t * 256 + (int)rank * 128;
            for (int kt = 0; kt < KT; kt++) {
                wait_parity(sb + SM_EMPTY + es * 8, ep);
                const uint32_t sa  = sb + SM_A + es * TILE_B;
                const uint32_t sbt = sb + SM_B + es * TILE_B;
                const int kb = kt * BK;
#pragma unroll
                for (int i = 0; i < 8; i++) {
                    cp16(sa  + swoff[i], A  + (size_t)(m0 + rowc[i]) * K + kb + colc[i] * 8);
                    cp16(sbt + swoff[i], Bm + (size_t)(n0 + rowc[i]) * K + kb + colc[i] * 8);
                }
                cp_arrive_noinc(sb + SM_FLOC + es * 8);
                if (++es == NSTAGE) { es = 0; ep ^= 1; }
            }
        }
    } else if (wid == 8) {
        // ======== MMA issuer / notifier ========
        if (elect_one()) {
            int ls = 0; uint32_t lp = 0;
            int fs = 0; uint32_t fp = 0;
            uint32_t efp[2] = {1, 1};
            for (int t = 0; t < TPP; t++) {
                const int buf = t & 1;
                const uint32_t dtm = tmem + buf * 256;
                for (int kt = 0; kt < KT; kt++) {
                    wait_parity(sb + SM_FLOC + ls * 8, lp);
                    fence_proxy_async_cta();
                    mbar_arrive_cluster(sb + SM_FULL + ls * 8, 0);
                    if (rank == 0) {
                        if (kt == 0) {
                            wait_parity(sb + SM_EPIF + buf * 8, efp[buf]);
                            efp[buf] ^= 1;
                        }
                        wait_parity(sb + SM_FULL + fs * 8, fp);
                        fence_after_sync();
                        const uint64_t ad = DESC_BASE | (((sb + SM_A + fs * TILE_B) >> 4) & 0x3FFF);
                        const uint64_t bd = DESC_BASE | (((sb + SM_B + fs * TILE_B) >> 4) & 0x3FFF);
#pragma unroll
                        for (int ks = 0; ks < 4; ks++)     // 4 x K=16 f16 MMAs
                            mma_cg2_f16(dtm, ad + ks * 2, bd + ks * 2,
                                        IDESC_F16, (kt > 0 || ks > 0) ? 1u : 0u);
                        commit_mc(sb + SM_EMPTY + fs * 8);
                        if (kt == KT - 1)
                            commit_mc(sb + SM_DONE + buf * 8);
                        if (++fs == NSTAGE) { fs = 0; fp ^= 1; }
                    }
                    if (++ls == NSTAGE) { ls = 0; lp ^= 1; }
                }
            }
        }
    } else {
        // ======== epilogue: warps 4-7, one TMEM subpartition each ========
        const int sub  = wid - 4;
        const int lane = tid & 31;
        const int grow = m0 + sub * 32 + lane;
        uint32_t dnp[2] = {0, 0};
        for (int t = 0; t < TPP; t++) {
            const int buf = t & 1;
            wait_parity(sb + SM_DONE + buf * 8, dnp[buf]);
            dnp[buf] ^= 1;
            fence_after_sync();
#pragma unroll
            for (int c4 = 0; c4 < 8; c4++) {
                uint32_t r[32];
                LDTM_X32(r, tmem + buf * 256 + c4 * 32);
                wait_ld();
                const int gc0 = t * 256 + c4 * 32;
#pragma unroll
                for (int j = 0; j < 32; j += 4) {
                    float4 bv = *(const float4*)(bias + gc0 + j);
                    float v0 = __uint_as_float(r[j])     + bv.x;
                    float v1 = __uint_as_float(r[j + 1]) + bv.y;
                    float v2 = __uint_as_float(r[j + 2]) + bv.z;
                    float v3 = __uint_as_float(r[j + 3]) + bv.w;
                    if (RELU) {
                        // ReLU then fp16-rn pack: inter stored as fp16 for GEMM2.
                        __half2 h01 = __floats2half2_rn(fmaxf(v0, 0.f), fmaxf(v1, 0.f));
                        __half2 h23 = __floats2half2_rn(fmaxf(v2, 0.f), fmaxf(v3, 0.f));
                        st_cs_h4((__half*)Cv + (size_t)grow * N + gc0 + j,
                                 *(uint32_t*)&h01, *(uint32_t*)&h23);
                    } else {
                        st_cs4((float*)Cv + (size_t)grow * N + gc0 + j, v0, v1, v2, v3);
                    }
                }
            }
            fence_before_sync();
            mbar_arrive_cluster(sb + SM_EPIF + buf * 8, 0);
        }
    }

    __syncthreads();
    if (wid == 8) tmem_dealloc_cg2(tmem, 512);
    cluster_sync();
#else
    // ================= fallback: legacy mma.sync fp16 (generic PTX pass) ========
    // A tile 128 x 64 halves (stride 72), B tile 256 x 64 halves, 2 stages.
    extern __shared__ __half smh[];
    const int tid  = threadIdx.x;
    const int lane = tid & 31;
    const int wid  = tid >> 5;
    const int m0 = blockIdx.y * 256 + blockIdx.x * 128;
    const int KT2 = K / 64;
    const int AT = 128 * 72;                 // halves
    const int BT = 256 * 72;
    const uint32_t s0 = smem_u32(smh);

    for (int t = 0; t < TPP; t++) {
        const int nb = t * 256;
        float acc[4][8][4];
        if (tid < 256) {
#pragma unroll
            for (int i = 0; i < 4; i++)
#pragma unroll
                for (int j = 0; j < 8; j++)
#pragma unroll
                    for (int c = 0; c < 4; c++) acc[i][j][c] = 0.f;
        }
        auto load_tile = [&](int kt, int st) {
            if (tid < 256) {
                const __half* Ag = A  + (size_t)m0 * K + (size_t)kt * 64;
                const __half* Bg = Bm + (size_t)nb * K + (size_t)kt * 64;
                const uint32_t sA = s0 + (uint32_t)(st * (AT + BT)) * 2;
                const uint32_t sB = sA + (uint32_t)AT * 2;
#pragma unroll
                for (int q = 0; q < 4; q++) {   // A: 1024 chunks (128 rows x 8)
                    int ch = tid + q * 256; int row = ch >> 3, c8 = ch & 7;
                    cp16(sA + (uint32_t)(row * 72 + c8 * 8) * 2, Ag + (size_t)row * K + c8 * 8);
                }
#pragma unroll
                for (int q = 0; q < 8; q++) {   // B: 2048 chunks (256 rows x 8)
                    int ch = tid + q * 256; int row = ch >> 3, c8 = ch & 7;
                    cp16(sB + (uint32_t)(row * 72 + c8 * 8) * 2, Bg + (size_t)row * K + c8 * 8);
                }
            }
            asm volatile("cp.async.commit_group;");
        };
        load_tile(0, 0);
        for (int kt = 0; kt < KT2; kt++) {
            const int st = kt & 1;
            if (kt + 1 < KT2) { load_tile(kt + 1, st ^ 1);
                                asm volatile("cp.async.wait_group 1;"); }
            else              { asm volatile("cp.async.wait_group 0;"); }
            __syncthreads();
            if (tid < 256) {
                const __half* As = smh + st * (AT + BT);
                const __half* Bs = As + AT;
                const int wm = wid >> 2, wn = wid & 3;   // 2x4 warp grid, 64x64 tiles
                const int g = lane >> 2, tg = lane & 3;
#pragma unroll
                for (int ks = 0; ks < 4; ks++) {         // 4 x K=16
                    const int k0 = ks * 16;
                    uint32_t af[4][4], bf[8][2];
#pragma unroll
                    for (int i = 0; i < 4; i++) {
                        const int r = wm * 64 + i * 16 + g;
                        af[i][0] = *(const uint32_t*)(As + (r    ) * 72 + k0 + 2 * tg);
                        af[i][1] = *(const uint32_t*)(As + (r + 8) * 72 + k0 + 2 * tg);
                        af[i][2] = *(const uint32_t*)(As + (r    ) * 72 + k0 + 2 * tg + 8);
                        af[i][3] = *(const uint32_t*)(As + (r + 8) * 72 + k0 + 2 * tg + 8);
                    }
#pragma unroll
                    for (int j = 0; j < 8; j++) {
                        const int c = wn * 64 + j * 8 + g;
                        bf[j][0] = *(const uint32_t*)(Bs + c * 72 + k0 + 2 * tg);
                        bf[j][1] = *(const uint32_t*)(Bs + c * 72 + k0 + 2 * tg + 8);
                    }
#pragma unroll
                    for (int i = 0; i < 4; i++)
#pragma unroll
                        for (int j = 0; j < 8; j++)
                            mma_f16(acc[i][j], af[i], bf[j]);
                }
            }
            __syncthreads();
        }
        if (tid < 256) {
            const int wm = wid >> 2, wn = wid & 3;
            const int g = lane >> 2, tg = lane & 3;
#pragma unroll
            for (int i = 0; i < 4; i++) {
                const int r0 = m0 + wm * 64 + i * 16 + g;
#pragma unroll
                for (int j = 0; j < 8; j++) {
                    const int c = nb + wn * 64 + j * 8 + tg * 2;
                    const float bv0 = bias[c], bv1 = bias[c + 1];
                    float v0 = acc[i][j][0] + bv0, v1 = acc[i][j][1] + bv1;
                    float v2 = acc[i][j][2] + bv0, v3 = acc[i][j][3] + bv1;
                    if (RELU) {
                        __half2 hA = __floats2half2_rn(fmaxf(v0, 0.f), fmaxf(v1, 0.f));
                        __half2 hB = __floats2half2_rn(fmaxf(v2, 0.f), fmaxf(v3, 0.f));
                        *(__half2*)((__half*)Cv + (size_t)r0 * N + c)       = hA;
                        *(__half2*)((__half*)Cv + (size_t)(r0 + 8) * N + c) = hB;
                    } else {
                        *(float2*)((float*)Cv + (size_t)r0 * N + c)       = make_float2(v0, v1);
                        *(float2*)((float*)Cv + (size_t)(r0 + 8) * N + c) = make_float2(v2, v3);
                    }
                }
            }
        }
        __syncthreads();
    }
#endif
}

// ---------------- launch ----------------
extern "C" void kernel_launch(void* const* d_in, const int* in_sizes, int n_in,
                              void* d_out, int out_size) {
    (void)in_sizes; (void)n_in; (void)out_size;
    const float* x  = (const float*)d_in[0];
    const float* W1 = (const float*)d_in[1];
    const float* b1 = (const float*)d_in[2];
    const float* W2 = (const float*)d_in[3];
    const float* b2 = (const float*)d_in[4];
    float* out = (float*)d_out;

    __half *inter, *xh, *w1h, *w2h;
    cudaGetSymbolAddress((void**)&inter, g_inter);
    cudaGetSymbolAddress((void**)&xh,  g_xh);
    cudaGetSymbolAddress((void**)&w1h, g_w1h);
    cudaGetSymbolAddress((void**)&w2h, g_w2h);

    cudaFuncSetAttribute(ffn_gemm<true>,
                         cudaFuncAttributeMaxDynamicSharedMemorySize, SMEM_TOTAL);
    cudaFuncSetAttribute(ffn_gemm<false>,
                         cudaFuncAttributeMaxDynamicSharedMemorySize, SMEM_TOTAL);

    // Prepass: f32 -> f16 (rn) of X, W1, W2 (inter produced fp16 by GEMM1).
    {
        int n8;
        n8 = MTOT * HID / 8;
        cvt_f16_kernel<<<(n8 + 255) / 256, 256>>>((const float4*)x,  (uint4*)xh,  n8);
        n8 = ITR * HID / 8;
        cvt_f16_kernel<<<(n8 + 255) / 256, 256>>>((const float4*)W1, (uint4*)w1h, n8);
        n8 = HID * ITR / 8;
        cvt_f16_kernel<<<(n8 + 255) / 256, 256>>>((const float4*)W2, (uint4*)w2h, n8);
    }

    // GEMM1: inter(f16) = ReLU(X @ W1^T + b1)  [16384,4096], K=1024
    ffn_gemm<true><<<dim3(2, MTOT / 256, 1), 288, SMEM_TOTAL>>>(
        xh, w1h, b1, inter, HID, ITR, ITR / 256);

    // GEMM2: out(f32) = inter @ W2^T + b2      [16384,1024], K=4096
    ffn_gemm<false><<<dim3(2, MTOT / 256, 1), 288, SMEM_TOTAL>>>(
        inter, w2h, b2, out, ITR, HID, HID / 256);
}

// round 14
// speedup vs baseline: 3.3762x; 1.0001x over previous
#include <cuda_runtime.h>
#include <cuda_fp16.h>
#include <cstdint>

#define HID  1024
#define ITR  4096
#define MTOT 16384

// Scratch: fp16 copies of X/W1/W2 and the fp16 intermediate ReLU(X@W1^T+b1).
__device__ __half g_inter[(size_t)MTOT * (size_t)ITR];
__device__ __half g_xh[(size_t)MTOT * (size_t)HID];
__device__ __half g_w1h[(size_t)ITR * (size_t)HID];
__device__ __half g_w2h[(size_t)HID * (size_t)ITR];

#if defined(__CUDA_ARCH_FEAT_SM103_ALL) || defined(__CUDA_ARCH_FEAT_SM100_ALL)
#define HAS_TC05 1
#else
#define HAS_TC05 0
#endif

// ---------------- smem layout ----------------
// Tile per pair: 256(M) x 512(N). Stage = A(16KB) + B(32KB: 2 x 16KB N-halves).
#define NSTAGE 4
#define BK 64                      // K (fp16) per stage
#define TILE_A 16384
#define TILE_BB 32768
#define STAGE_B (TILE_A + TILE_BB) // 49152
#define SM_TMEM  0
#define SM_FULL  16                // [4] pair-full on leader (count 2)
#define SM_FLOC  48                // [4] local cp.async barrier (count 128)
#define SM_EMPTY 80                // [4] stage free (commit multicast)
#define SM_DONE  112               // tile done (commit multicast)
#define SM_EPIF  120               // epilogue freed D (count 256, on leader)
#define SM_OPS 1024
#define SMEM_TOTAL (SM_OPS + NSTAGE * STAGE_B)   // 197632 B

// idesc kind::f16 fp16: c=F32(1)<<4 | a=FP16<<7 | b=FP16<<10 | (256/8)<<17 | (256/16)<<24
#define IDESC_F16 0x10400010u
static constexpr uint64_t DESC_BASE =       // SW128 K-major: layout=2, ver=1, SBO=64, LBO=1
    (2ull << 61) | (1ull << 46) | (64ull << 32) | (1ull << 16);

// ---------------- common helpers ----------------
__device__ __forceinline__ uint32_t smem_u32(const void* p) {
    return (uint32_t)__cvta_generic_to_shared(p);
}
__device__ __forceinline__ void cp16(uint32_t d, const void* s) {
    asm volatile("cp.async.cg.shared.global [%0], [%1], 16;" :: "r"(d), "l"(s));
}
__device__ __forceinline__ void st_cs4(float* p, float a, float b, float c, float d) {
    asm volatile("st.global.cs.v4.f32 [%0], {%1,%2,%3,%4};"
                 :: "l"(p), "f"(a), "f"(b), "f"(c), "f"(d) : "memory");
}
__device__ __forceinline__ void st_cs_h4(__half* p, uint32_t h01, uint32_t h23) {
    asm volatile("st.global.cs.v2.b32 [%0], {%1,%2};"
                 :: "l"(p), "r"(h01), "r"(h23) : "memory");
}

// ---------------- prepass: f32 -> f16 (rn), 8 elems/thread ----------------
__global__ void __launch_bounds__(256) cvt_f16_kernel(const float4* __restrict__ in,
                                                      uint4* __restrict__ out, int n8) {
    int i = blockIdx.x * blockDim.x + threadIdx.x;
    if (i < n8) {
        float4 a = in[2 * i], b = in[2 * i + 1];
        __half2 h0 = __floats2half2_rn(a.x, a.y);
        __half2 h1 = __floats2half2_rn(a.z, a.w);
        __half2 h2 = __floats2half2_rn(b.x, b.y);
        __half2 h3 = __floats2half2_rn(b.z, b.w);
        uint4 o;
        o.x = *(uint32_t*)&h0; o.y = *(uint32_t*)&h1;
        o.z = *(uint32_t*)&h2; o.w = *(uint32_t*)&h3;
        out[i] = o;
    }
}

#if HAS_TC05
// ---------------- tcgen05 helpers ----------------
__device__ __forceinline__ uint32_t ctarank() {
    uint32_t r; asm("mov.u32 %0, %%cluster_ctarank;" : "=r"(r)); return r;
}
__device__ __forceinline__ bool elect_one() {
    uint32_t p;
    asm volatile("{\n\t.reg .pred P;\n\telect.sync _|P, 0xFFFFFFFF;\n\tselp.b32 %0, 1, 0, P;\n\t}"
                 : "=r"(p));
    return p != 0;
}
__device__ __forceinline__ void mbar_init(uint32_t a, uint32_t cnt) {
    asm volatile("mbarrier.init.shared.b64 [%0], %1;" :: "r"(a), "r"(cnt) : "memory");
}
__device__ __forceinline__ void mbar_arrive_cluster(uint32_t local_addr, uint32_t rank) {
    asm volatile("{\n\t.reg .b32 ra;\n\tmapa.shared::cluster.u32 ra, %0, %1;\n\t"
                 "mbarrier.arrive.shared::cluster.b64 _, [ra];\n\t}"
                 :: "r"(local_addr), "r"(rank) : "memory");
}
__device__ __forceinline__ void wait_parity(uint32_t a, uint32_t ph) {
    asm volatile("{\n\t.reg .pred P;\n"
                 "W_%=:\n\tmbarrier.try_wait.parity.acquire.cta.shared::cta.b64 P, [%0], %1, 0x989680;\n"
                 "\t@P bra D_%=;\n\tbra W_%=;\nD_%=:\n\t}"
                 :: "r"(a), "r"(ph) : "memory");
}
__device__ __forceinline__ void cp_arrive_noinc(uint32_t bar) {
    asm volatile("cp.async.mbarrier.arrive.noinc.shared::cta.b64 [%0];" :: "r"(bar) : "memory");
}
__device__ __forceinline__ void mma_cg2_f16(uint32_t d, uint64_t ad, uint64_t bd,
                                            uint32_t idesc, uint32_t en) {
    asm volatile("{\n\t.reg .pred p;\n\tsetp.ne.u32 p, %4, 0;\n\t"
                 "tcgen05.mma.cta_group::2.kind::f16 [%0], %1, %2, %3, "
                 "{%5,%5,%5,%5,%5,%5,%5,%5}, p;\n\t}"
                 :: "r"(d), "l"(ad), "l"(bd), "r"(idesc), "r"(en), "r"(0u) : "memory");
}
__device__ __forceinline__ void commit_mc(uint32_t bar) {
    asm volatile("tcgen05.commit.cta_group::2.mbarrier::arrive::one.shared::cluster.multicast::cluster.b64 [%0], %1;"
                 :: "r"(bar), "h"((uint16_t)3) : "memory");
}
__device__ __forceinline__ void tmem_alloc_cg2(uint32_t addr, uint32_t ncols) {
    asm volatile("tcgen05.alloc.cta_group::2.sync.aligned.shared::cta.b32 [%0], %1;"
                 :: "r"(addr), "r"(ncols) : "memory");
}
__device__ __forceinline__ void tmem_dealloc_cg2(uint32_t tmem, uint32_t ncols) {
    asm volatile("tcgen05.dealloc.cta_group::2.sync.aligned.b32 %0, %1;" :: "r"(tmem), "r"(ncols));
}
__device__ __forceinline__ void tmem_relinquish_cg2() {
    asm volatile("tcgen05.relinquish_alloc_permit.cta_group::2.sync.aligned;");
}
__device__ __forceinline__ void fence_after_sync() {
    asm volatile("tcgen05.fence::after_thread_sync;" ::: "memory");
}
__device__ __forceinline__ void fence_before_sync() {
    asm volatile("tcgen05.fence::before_thread_sync;" ::: "memory");
}
__device__ __forceinline__ void fence_proxy_async_cta() {
    asm volatile("fence.proxy.async.shared::cta;" ::: "memory");
}
__device__ __forceinline__ void cluster_sync() {
    asm volatile("barrier.cluster.arrive.aligned;" ::: "memory");
    asm volatile("barrier.cluster.wait.aligned;" ::: "memory");
}
__device__ __forceinline__ void wait_ld() {
    asm volatile("tcgen05.wait::ld.sync.aligned;" ::: "memory");
}
#define LDTM_X32(r, taddr) \
    asm volatile( \
        "tcgen05.ld.sync.aligned.32x32b.x32.b32 " \
        "{%0, %1, %2, %3, %4, %5, %6, %7, " \
        " %8, %9, %10, %11, %12, %13, %14, %15, " \
        " %16, %17, %18, %19, %20, %21, %22, %23, " \
        " %24, %25, %26, %27, %28, %29, %30, %31}, [%32];" \
        : "=r"((r)[0]),  "=r"((r)[1]),  "=r"((r)[2]),  "=r"((r)[3]), \
          "=r"((r)[4]),  "=r"((r)[5]),  "=r"((r)[6]),  "=r"((r)[7]), \
          "=r"((r)[8]),  "=r"((r)[9]),  "=r"((r)[10]), "=r"((r)[11]), \
          "=r"((r)[12]), "=r"((r)[13]), "=r"((r)[14]), "=r"((r)[15]), \
          "=r"((r)[16]), "=r"((r)[17]), "=r"((r)[18]), "=r"((r)[19]), \
          "=r"((r)[20]), "=r"((r)[21]), "=r"((r)[22]), "=r"((r)[23]), \
          "=r"((r)[24]), "=r"((r)[25]), "=r"((r)[26]), "=r"((r)[27]), \
          "=r"((r)[28]), "=r"((r)[29]), "=r"((r)[30]), "=r"((r)[31]) \
        : "r"(taddr))
#else
__device__ __forceinline__ void mma_f16(float* d, const uint32_t* a, const uint32_t* b) {
    asm volatile(
        "mma.sync.aligned.m16n8k16.row.col.f32.f16.f16.f32 "
        "{%0,%1,%2,%3}, {%4,%5,%6,%7}, {%8,%9}, {%0,%1,%2,%3};\n"
        : "+f"(d[0]), "+f"(d[1]), "+f"(d[2]), "+f"(d[3])
        : "r"(a[0]), "r"(a[1]), "r"(a[2]), "r"(a[3]), "r"(b[0]), "r"(b[1]));
}
#endif

// ---------------- kernel ----------------
// grid = (2, M/256), cluster (2,1,1), 288 threads, persistent over TPP N-tiles
// of width 512. Warps 0-3 produce, warps 4-7 epilogue (512 cols), warp 8 MMA.
// Per k-tile: 2 cg2 MMAs (N-halves, D cols 0-255 / 256-511, shared A desc).
template <bool RELU>
__global__ void __launch_bounds__(288, 1) __cluster_dims__(2, 1, 1)
ffn_gemm(const __half* __restrict__ A, const __half* __restrict__ Bm,
         const float* __restrict__ bias, void* __restrict__ Cv,
         int K, int N, int TPP)
{
#if HAS_TC05
    extern __shared__ __align__(1024) char smem[];
    const uint32_t sb  = smem_u32(smem);
    const int tid = threadIdx.x;
    const int wid = tid >> 5;
    const uint32_t rank = ctarank();

    const int m0 = blockIdx.y * 256 + (int)rank * 128;
    const int KT = K / BK;

    if (wid == 8) {
        tmem_alloc_cg2(sb + SM_TMEM, 512);
        tmem_relinquish_cg2();
    }
    if (tid == 0) {
#pragma unroll
        for (int s = 0; s < NSTAGE; s++) {
            mbar_init(sb + SM_FULL  + s * 8, 2);
            mbar_init(sb + SM_FLOC  + s * 8, 128);
            mbar_init(sb + SM_EMPTY + s * 8, 1);
        }
        mbar_init(sb + SM_DONE, 1);
        mbar_init(sb + SM_EPIF, 256);
    }
    __syncthreads();
    uint32_t tmem;
    asm volatile("ld.shared.b32 %0, [%1];" : "=r"(tmem) : "r"(sb + SM_TMEM));
    cluster_sync();

    if (wid < 4) {
        // ======== producers: 128 threads, 24 cp16/thread/stage ========
        // chunks 0..1023: A (128 rows x 8); 1024..3071: B (256 rows x 8).
        // B row b: N-half h=b>>7, local row l=b&127; global = n0 + h*256 + rank*128 + l.
        uint32_t soff[24]; int grow_[24], gcol[24]; bool isA[24];
#pragma unroll
        for (int i = 0; i < 24; i++) {
            int chunk = tid + i * 128;
            if (chunk < 1024) {
                int row = chunk >> 3, c = chunk & 7;
                uint32_t off = (uint32_t)(row * 128 + c * 16);
                soff[i] = off ^ ((off >> 3) & 0x70);
                grow_[i] = row; gcol[i] = c; isA[i] = true;
            } else {
                int idx = chunk - 1024;
                int b = idx >> 3, c = idx & 7;
                int h = b >> 7, l = b & 127;
                uint32_t off = (uint32_t)(l * 128 + c * 16);
                soff[i] = (uint32_t)(TILE_A + h * 16384) + (off ^ ((off >> 3) & 0x70));
                grow_[i] = h * 256 + (int)rank * 128 + l;   // + t*512 at runtime
                gcol[i] = c; isA[i] = false;
            }
        }
        int es = 0; uint32_t ep = 1;
        for (int t = 0; t < TPP; t++) {
            const int n0 = t * 512;
            for (int kt = 0; kt < KT; kt++) {
                wait_parity(sb + SM_EMPTY + es * 8, ep);
                const uint32_t sbase = sb + SM_OPS + es * STAGE_B;
                const int kb = kt * BK;
#pragma unroll
                for (int i = 0; i < 24; i++) {
                    const __half* src = isA[i]
                        ? A  + (size_t)(m0 + grow_[i]) * K + kb + gcol[i] * 8
                        : Bm + (size_t)(n0 + grow_[i]) * K + kb + gcol[i] * 8;
                    cp16(sbase + soff[i], src);
                }
                cp_arrive_noinc(sb + SM_FLOC + es * 8);
                if (++es == NSTAGE) { es = 0; ep ^= 1; }
            }
        }
    } else if (wid == 8) {
        // ======== MMA issuer / notifier ========
        if (elect_one()) {
            int ls = 0; uint32_t lp = 0;
            int fs = 0; uint32_t fp = 0;
            uint32_t efp = 1;
            for (int t = 0; t < TPP; t++) {
                for (int kt = 0; kt < KT; kt++) {
                    wait_parity(sb + SM_FLOC + ls * 8, lp);
                    fence_proxy_async_cta();
                    mbar_arrive_cluster(sb + SM_FULL + ls * 8, 0);
                    if (rank == 0) {
                        if (kt == 0) {                    // D drained?
                            wait_parity(sb + SM_EPIF, efp);
                            efp ^= 1;
                        }
                        wait_parity(sb + SM_FULL + fs * 8, fp);
                        fence_after_sync();
                        const uint32_t st = sb + SM_OPS + fs * STAGE_B;
                        const uint64_t ad = DESC_BASE | (((st) >> 4) & 0x3FFF);
#pragma unroll
                        for (int h = 0; h < 2; h++) {
                            const uint64_t bd = DESC_BASE |
                                (((st + TILE_A + h * 16384) >> 4) & 0x3FFF);
#pragma unroll
                            for (int ks = 0; ks < 4; ks++)
                                mma_cg2_f16(tmem + h * 256, ad + ks * 2, bd + ks * 2,
                                            IDESC_F16, (kt > 0 || ks > 0) ? 1u : 0u);
                        }
                        commit_mc(sb + SM_EMPTY + fs * 8);
                        if (kt == KT - 1)
                            commit_mc(sb + SM_DONE);
                        if (++fs == NSTAGE) { fs = 0; fp ^= 1; }
                    }
                    if (++ls == NSTAGE) { ls = 0; lp ^= 1; }
                }
            }
        }
    } else {
        // ======== epilogue: warps 4-7, 512 cols, one subpartition each ========
        const int sub  = wid - 4;
        const int lane = tid & 31;
        const int grow = m0 + sub * 32 + lane;
        uint32_t dnp = 0;
        for (int t = 0; t < TPP; t++) {
            wait_parity(sb + SM_DONE, dnp);
            dnp ^= 1;
            fence_after_sync();
#pragma unroll
            for (int c4 = 0; c4 < 16; c4++) {
                uint32_t r[32];
                LDTM_X32(r, tmem + c4 * 32);
                wait_ld();
                const int gc0 = t * 512 + c4 * 32;
#pragma unroll
                for (int j = 0; j < 32; j += 4) {
                    float4 bv = *(const float4*)(bias + gc0 + j);
                    float v0 = __uint_as_float(r[j])     + bv.x;
                    float v1 = __uint_as_float(r[j + 1]) + bv.y;
                    float v2 = __uint_as_float(r[j + 2]) + bv.z;
                    float v3 = __uint_as_float(r[j + 3]) + bv.w;
                    if (RELU) {
                        __half2 h01 = __floats2half2_rn(fmaxf(v0, 0.f), fmaxf(v1, 0.f));
                        __half2 h23 = __floats2half2_rn(fmaxf(v2, 0.f), fmaxf(v3, 0.f));
                        st_cs_h4((__half*)Cv + (size_t)grow * N + gc0 + j,
                                 *(uint32_t*)&h01, *(uint32_t*)&h23);
                    } else {
                        st_cs4((float*)Cv + (size_t)grow * N + gc0 + j, v0, v1, v2, v3);
                    }
                }
            }
            fence_before_sync();
            mbar_arrive_cluster(sb + SM_EPIF, 0);
        }
    }

    __syncthreads();
    if (wid == 8) tmem_dealloc_cg2(tmem, 512);
    cluster_sync();
#else
    // ================= fallback: legacy mma.sync fp16 (generic PTX pass) ========
    // 256-wide tiles, 2*TPP of them. A 128x64 halves (stride 72), B 256x64.
    extern __shared__ __half smh[];
    const int tid  = threadIdx.x;
    const int lane = tid & 31;
    const int wid  = tid >> 5;
    const int m0 = blockIdx.y * 256 + blockIdx.x * 128;
    const int KT2 = K / 64;
    const int AT = 128 * 72;
    const int BT = 256 * 72;
    const uint32_t s0 = smem_u32(smh);

    for (int t = 0; t < 2 * TPP; t++) {
        const int nb = t * 256;
        float acc[4][8][4];
        if (tid < 256) {
#pragma unroll
            for (int i = 0; i < 4; i++)
#pragma unroll
                for (int j = 0; j < 8; j++)
#pragma unroll
                    for (int c = 0; c < 4; c++) acc[i][j][c] = 0.f;
        }
        auto load_tile = [&](int kt, int st) {
            if (tid < 256) {
                const __half* Ag = A  + (size_t)m0 * K + (size_t)kt * 64;
                const __half* Bg = Bm + (size_t)nb * K + (size_t)kt * 64;
                const uint32_t sA = s0 + (uint32_t)(st * (AT + BT)) * 2;
                const uint32_t sB = sA + (uint32_t)AT * 2;
#pragma unroll
                for (int q = 0; q < 4; q++) {
                    int ch = tid + q * 256; int row = ch >> 3, c8 = ch & 7;
                    cp16(sA + (uint32_t)(row * 72 + c8 * 8) * 2, Ag + (size_t)row * K + c8 * 8);
                }
#pragma unroll
                for (int q = 0; q < 8; q++) {
                    int ch = tid + q * 256; int row = ch >> 3, c8 = ch & 7;
                    cp16(sB + (uint32_t)(row * 72 + c8 * 8) * 2, Bg + (size_t)row * K + c8 * 8);
                }
            }
            asm volatile("cp.async.commit_group;");
        };
        load_tile(0, 0);
        for (int kt = 0; kt < KT2; kt++) {
            const int st = kt & 1;
            if (kt + 1 < KT2) { load_tile(kt + 1, st ^ 1);
                                asm volatile("cp.async.wait_group 1;"); }
            else              { asm volatile("cp.async.wait_group 0;"); }
            __syncthreads();
            if (tid < 256) {
                const __half* As = smh + st * (AT + BT);
                const __half* Bs = As + AT;
                const int wm = wid >> 2, wn = wid & 3;
                const int g = lane >> 2, tg = lane & 3;
#pragma unroll
                for (int ks = 0; ks < 4; ks++) {
                    const int k0 = ks * 16;
                    uint32_t af[4][4], bf[8][2];
#pragma unroll
                    for (int i = 0; i < 4; i++) {
                        const int r = wm * 64 + i * 16 + g;
                        af[i][0] = *(const uint32_t*)(As + (r    ) * 72 + k0 + 2 * tg);
                        af[i][1] = *(const uint32_t*)(As + (r + 8) * 72 + k0 + 2 * tg);
                        af[i][2] = *(const uint32_t*)(As + (r    ) * 72 + k0 + 2 * tg + 8);
                        af[i][3] = *(const uint32_t*)(As + (r + 8) * 72 + k0 + 2 * tg + 8);
                    }
#pragma unroll
                    for (int j = 0; j < 8; j++) {
                        const int c = wn * 64 + j * 8 + g;
                        bf[j][0] = *(const uint32_t*)(Bs + c * 72 + k0 + 2 * tg);
                        bf[j][1] = *(const uint32_t*)(Bs + c * 72 + k0 + 2 * tg + 8);
                    }
#pragma unroll
                    for (int i = 0; i < 4; i++)
#pragma unroll
                        for (int j = 0; j < 8; j++)
                            mma_f16(acc[i][j], af[i], bf[j]);
                }
            }
            __syncthreads();
        }
        if (tid < 256) {
            const int wm = wid >> 2, wn = wid & 3;
            const int g = lane >> 2, tg = lane & 3;
#pragma unroll
            for (int i = 0; i < 4; i++) {
                const int r0 = m0 + wm * 64 + i * 16 + g;
#pragma unroll
                for (int j = 0; j < 8; j++) {
                    const int c = nb + wn * 64 + j * 8 + tg * 2;
                    const float bv0 = bias[c], bv1 = bias[c + 1];
                    float v0 = acc[i][j][0] + bv0, v1 = acc[i][j][1] + bv1;
                    float v2 = acc[i][j][2] + bv0, v3 = acc[i][j][3] + bv1;
                    if (RELU) {
                        __half2 hA = __floats2half2_rn(fmaxf(v0, 0.f), fmaxf(v1, 0.f));
                        __half2 hB = __floats2half2_rn(fmaxf(v2, 0.f), fmaxf(v3, 0.f));
                        *(__half2*)((__half*)Cv + (size_t)r0 * N + c)       = hA;
                        *(__half2*)((__half*)Cv + (size_t)(r0 + 8) * N + c) = hB;
                    } else {
                        *(float2*)((float*)Cv + (size_t)r0 * N + c)       = make_float2(v0, v1);
                        *(float2*)((float*)Cv + (size_t)(r0 + 8) * N + c) = make_float2(v2, v3);
                    }
                }
            }
        }
        __syncthreads();
    }
#endif
}

// ---------------- launch ----------------
extern "C" void kernel_launch(void* const* d_in, const int* in_sizes, int n_in,
                              void* d_out, int out_size) {
    (void)in_sizes; (void)n_in; (void)out_size;
    const float* x  = (const float*)d_in[0];
    const float* W1 = (const float*)d_in[1];
    const float* b1 = (const float*)d_in[2];
    const float* W2 = (const float*)d_in[3];
    const float* b2 = (const float*)d_in[4];
    float* out = (float*)d_out;

    __half *inter, *xh, *w1h, *w2h;
    cudaGetSymbolAddress((void**)&inter, g_inter);
    cudaGetSymbolAddress((void**)&xh,  g_xh);
    cudaGetSymbolAddress((void**)&w1h, g_w1h);
    cudaGetSymbolAddress((void**)&w2h, g_w2h);

    cudaFuncSetAttribute(ffn_gemm<true>,
                         cudaFuncAttributeMaxDynamicSharedMemorySize, SMEM_TOTAL);
    cudaFuncSetAttribute(ffn_gemm<false>,
                         cudaFuncAttributeMaxDynamicSharedMemorySize, SMEM_TOTAL);

    // Prepass: f32 -> f16 (rn) of X, W1, W2.
    {
        int n8;
        n8 = MTOT * HID / 8;
        cvt_f16_kernel<<<(n8 + 255) / 256, 256>>>((const float4*)x,  (uint4*)xh,  n8);
        n8 = ITR * HID / 8;
        cvt_f16_kernel<<<(n8 + 255) / 256, 256>>>((const float4*)W1, (uint4*)w1h, n8);
        n8 = HID * ITR / 8;
        cvt_f16_kernel<<<(n8 + 255) / 256, 256>>>((const float4*)W2, (uint4*)w2h, n8);
    }

    // GEMM1: inter(f16) = ReLU(X @ W1^T + b1)  [16384,4096], K=1024, 8 tiles of 512
    ffn_gemm<true><<<dim3(2, MTOT / 256, 1), 288, SMEM_TOTAL>>>(
        xh, w1h, b1, inter, HID, ITR, ITR / 512);

    // GEMM2: out(f32) = inter @ W2^T + b2      [16384,1024], K=4096, 2 tiles of 512
    ffn_gemm<false><<<dim3(2, MTOT / 256, 1), 288, SMEM_TOTAL>>>(
        inter, w2h, b2, out, ITR, HID, HID / 512);
}

// round 15
// speedup vs baseline: 3.3874x; 1.0033x over previous
#include <cuda_runtime.h>
#include <cuda_fp16.h>
#include <cstdint>

#define HID  1024
#define ITR  4096
#define MTOT 16384

// Scratch: fp16 copies of X/W1/W2 and the fp16 intermediate ReLU(X@W1^T+b1).
__device__ __half g_inter[(size_t)MTOT * (size_t)ITR];
__device__ __half g_xh[(size_t)MTOT * (size_t)HID];
__device__ __half g_w1h[(size_t)ITR * (size_t)HID];
__device__ __half g_w2h[(size_t)HID * (size_t)ITR];

#if defined(__CUDA_ARCH_FEAT_SM103_ALL) || defined(__CUDA_ARCH_FEAT_SM100_ALL)
#define HAS_TC05 1
#else
#define HAS_TC05 0
#endif

// ---------------- smem layout ----------------
// Tile per pair: 256(M) x 512(N). Stage = A(16KB) + B(32KB: 2 x 16KB N-halves).
#define NSTAGE 4
#define BK 64                      // K (fp16) per stage
#define TILE_A 16384
#define TILE_BB 32768
#define STAGE_B (TILE_A + TILE_BB) // 49152
#define SM_TMEM  0
#define SM_FULL  16                // [4] pair-full on leader (count 2)
#define SM_FLOC  48                // [4] local cp.async barrier (count 128)
#define SM_EMPTY 80                // [4] stage free (commit multicast)
#define SM_DONE  112               // tile done (commit multicast)
#define SM_EPIF  120               // epilogue freed D (count 256, on leader)
#define SM_OPS 1024
#define SMEM_TOTAL (SM_OPS + NSTAGE * STAGE_B)   // 197632 B

// idesc kind::f16 fp16: c=F32(1)<<4 | a=FP16<<7 | b=FP16<<10 | (256/8)<<17 | (256/16)<<24
#define IDESC_F16 0x10400010u
static constexpr uint64_t DESC_BASE =       // SW128 K-major: layout=2, ver=1, SBO=64, LBO=1
    (2ull << 61) | (1ull << 46) | (64ull << 32) | (1ull << 16);

// ---------------- common helpers ----------------
__device__ __forceinline__ uint32_t smem_u32(const void* p) {
    return (uint32_t)__cvta_generic_to_shared(p);
}
__device__ __forceinline__ void cp16(uint32_t d, const void* s) {
    asm volatile("cp.async.cg.shared.global [%0], [%1], 16;" :: "r"(d), "l"(s));
}
__device__ __forceinline__ void st_cs4(float* p, float a, float b, float c, float d) {
    asm volatile("st.global.cs.v4.f32 [%0], {%1,%2,%3,%4};"
                 :: "l"(p), "f"(a), "f"(b), "f"(c), "f"(d) : "memory");
}
__device__ __forceinline__ void st_cs_h4(__half* p, uint32_t h01, uint32_t h23) {
    asm volatile("st.global.cs.v2.b32 [%0], {%1,%2};"
                 :: "l"(p), "r"(h01), "r"(h23) : "memory");
}

// ---------------- prepass: f32 -> f16 (rn), 8 elems/thread ----------------
__global__ void __launch_bounds__(256) cvt_f16_kernel(const float4* __restrict__ in,
                                                      uint4* __restrict__ out, int n8) {
    int i = blockIdx.x * blockDim.x + threadIdx.x;
    if (i < n8) {
        float4 a = in[2 * i], b = in[2 * i + 1];
        __half2 h0 = __floats2half2_rn(a.x, a.y);
        __half2 h1 = __floats2half2_rn(a.z, a.w);
        __half2 h2 = __floats2half2_rn(b.x, b.y);
        __half2 h3 = __floats2half2_rn(b.z, b.w);
        uint4 o;
        o.x = *(uint32_t*)&h0; o.y = *(uint32_t*)&h1;
        o.z = *(uint32_t*)&h2; o.w = *(uint32_t*)&h3;
        out[i] = o;
    }
}

#if HAS_TC05
// ---------------- tcgen05 helpers ----------------
__device__ __forceinline__ uint32_t ctarank() {
    uint32_t r; asm("mov.u32 %0, %%cluster_ctarank;" : "=r"(r)); return r;
}
__device__ __forceinline__ bool elect_one() {
    uint32_t p;
    asm volatile("{\n\t.reg .pred P;\n\telect.sync _|P, 0xFFFFFFFF;\n\tselp.b32 %0, 1, 0, P;\n\t}"
                 : "=r"(p));
    return p != 0;
}
__device__ __forceinline__ void mbar_init(uint32_t a, uint32_t cnt) {
    asm volatile("mbarrier.init.shared.b64 [%0], %1;" :: "r"(a), "r"(cnt) : "memory");
}
__device__ __forceinline__ void mbar_arrive_cluster(uint32_t local_addr, uint32_t rank) {
    asm volatile("{\n\t.reg .b32 ra;\n\tmapa.shared::cluster.u32 ra, %0, %1;\n\t"
                 "mbarrier.arrive.shared::cluster.b64 _, [ra];\n\t}"
                 :: "r"(local_addr), "r"(rank) : "memory");
}
__device__ __forceinline__ void wait_parity(uint32_t a, uint32_t ph) {
    asm volatile("{\n\t.reg .pred P;\n"
                 "W_%=:\n\tmbarrier.try_wait.parity.acquire.cta.shared::cta.b64 P, [%0], %1, 0x989680;\n"
                 "\t@P bra D_%=;\n\tbra W_%=;\nD_%=:\n\t}"
                 :: "r"(a), "r"(ph) : "memory");
}
__device__ __forceinline__ void cp_arrive_noinc(uint32_t bar) {
    asm volatile("cp.async.mbarrier.arrive.noinc.shared::cta.b64 [%0];" :: "r"(bar) : "memory");
}
__device__ __forceinline__ void mma_cg2_f16(uint32_t d, uint64_t ad, uint64_t bd,
                                            uint32_t idesc, uint32_t en) {
    asm volatile("{\n\t.reg .pred p;\n\tsetp.ne.u32 p, %4, 0;\n\t"
                 "tcgen05.mma.cta_group::2.kind::f16 [%0], %1, %2, %3, "
                 "{%5,%5,%5,%5,%5,%5,%5,%5}, p;\n\t}"
                 :: "r"(d), "l"(ad), "l"(bd), "r"(idesc), "r"(en), "r"(0u) : "memory");
}
__device__ __forceinline__ void commit_mc(uint32_t bar) {
    asm volatile("tcgen05.commit.cta_group::2.mbarrier::arrive::one.shared::cluster.multicast::cluster.b64 [%0], %1;"
                 :: "r"(bar), "h"((uint16_t)3) : "memory");
}
__device__ __forceinline__ void tmem_alloc_cg2(uint32_t addr, uint32_t ncols) {
    asm volatile("tcgen05.alloc.cta_group::2.sync.aligned.shared::cta.b32 [%0], %1;"
                 :: "r"(addr), "r"(ncols) : "memory");
}
__device__ __forceinline__ void tmem_dealloc_cg2(uint32_t tmem, uint32_t ncols) {
    asm volatile("tcgen05.dealloc.cta_group::2.sync.aligned.b32 %0, %1;" :: "r"(tmem), "r"(ncols));
}
__device__ __forceinline__ void tmem_relinquish_cg2() {
    asm volatile("tcgen05.relinquish_alloc_permit.cta_group::2.sync.aligned;");
}
__device__ __forceinline__ void fence_after_sync() {
    asm volatile("tcgen05.fence::after_thread_sync;" ::: "memory");
}
__device__ __forceinline__ void fence_before_sync() {
    asm volatile("tcgen05.fence::before_thread_sync;" ::: "memory");
}
__device__ __forceinline__ void fence_proxy_async_cta() {
    asm volatile("fence.proxy.async.shared::cta;" ::: "memory");
}
__device__ __forceinline__ void cluster_sync() {
    asm volatile("barrier.cluster.arrive.aligned;" ::: "memory");
    asm volatile("barrier.cluster.wait.aligned;" ::: "memory");
}
__device__ __forceinline__ void wait_ld() {
    asm volatile("tcgen05.wait::ld.sync.aligned;" ::: "memory");
}
#define LDTM_X32(r, taddr) \
    asm volatile( \
        "tcgen05.ld.sync.aligned.32x32b.x32.b32 " \
        "{%0, %1, %2, %3, %4, %5, %6, %7, " \
        " %8, %9, %10, %11, %12, %13, %14, %15, " \
        " %16, %17, %18, %19, %20, %21, %22, %23, " \
        " %24, %25, %26, %27, %28, %29, %30, %31}, [%32];" \
        : "=r"((r)[0]),  "=r"((r)[1]),  "=r"((r)[2]),  "=r"((r)[3]), \
          "=r"((r)[4]),  "=r"((r)[5]),  "=r"((r)[6]),  "=r"((r)[7]), \
          "=r"((r)[8]),  "=r"((r)[9]),  "=r"((r)[10]), "=r"((r)[11]), \
          "=r"((r)[12]), "=r"((r)[13]), "=r"((r)[14]), "=r"((r)[15]), \
          "=r"((r)[16]), "=r"((r)[17]), "=r"((r)[18]), "=r"((r)[19]), \
          "=r"((r)[20]), "=r"((r)[21]), "=r"((r)[22]), "=r"((r)[23]), \
          "=r"((r)[24]), "=r"((r)[25]), "=r"((r)[26]), "=r"((r)[27]), \
          "=r"((r)[28]), "=r"((r)[29]), "=r"((r)[30]), "=r"((r)[31]) \
        : "r"(taddr))
#else
__device__ __forceinline__ void mma_f16(float* d, const uint32_t* a, const uint32_t* b) {
    asm volatile(
        "mma.sync.aligned.m16n8k16.row.col.f32.f16.f16.f32 "
        "{%0,%1,%2,%3}, {%4,%5,%6,%7}, {%8,%9}, {%0,%1,%2,%3};\n"
        : "+f"(d[0]), "+f"(d[1]), "+f"(d[2]), "+f"(d[3])
        : "r"(a[0]), "r"(a[1]), "r"(a[2]), "r"(a[3]), "r"(b[0]), "r"(b[1]));
}
#endif

// ---------------- kernel ----------------
// grid = (2, M/256), cluster (2,1,1), 288 threads, persistent over TPP N-tiles
// of width 512. Warps 0-3 produce, warps 4-7 epilogue (512 cols), warp 8 MMA.
// Per k-tile: 2 cg2 MMAs (N-halves, D cols 0-255 / 256-511, shared A desc).
template <bool RELU>
__global__ void __launch_bounds__(288, 1) __cluster_dims__(2, 1, 1)
ffn_gemm(const __half* __restrict__ A, const __half* __restrict__ Bm,
         const float* __restrict__ bias, void* __restrict__ Cv,
         int K, int N, int TPP)
{
#if HAS_TC05
    extern __shared__ __align__(1024) char smem[];
    const uint32_t sb  = smem_u32(smem);
    const int tid = threadIdx.x;
    const int wid = tid >> 5;
    const uint32_t rank = ctarank();

    const int m0 = blockIdx.y * 256 + (int)rank * 128;
    const int KT = K / BK;

    if (wid == 8) {
        tmem_alloc_cg2(sb + SM_TMEM, 512);
        tmem_relinquish_cg2();
    }
    if (tid == 0) {
#pragma unroll
        for (int s = 0; s < NSTAGE; s++) {
            mbar_init(sb + SM_FULL  + s * 8, 2);
            mbar_init(sb + SM_FLOC  + s * 8, 128);
            mbar_init(sb + SM_EMPTY + s * 8, 1);
        }
        mbar_init(sb + SM_DONE, 1);
        mbar_init(sb + SM_EPIF, 256);
    }
    __syncthreads();
    uint32_t tmem;
    asm volatile("ld.shared.b32 %0, [%1];" : "=r"(tmem) : "r"(sb + SM_TMEM));
    cluster_sync();

    if (wid < 4) {
        // ======== producers: 128 threads, 24 cp16/thread/stage ========
        // chunks 0..1023: A (128 rows x 8); 1024..3071: B (256 rows x 8).
        // B row b: N-half h=b>>7, local row l=b&127; global = n0 + h*256 + rank*128 + l.
        uint32_t soff[24]; int grow_[24], gcol[24]; bool isA[24];
#pragma unroll
        for (int i = 0; i < 24; i++) {
            int chunk = tid + i * 128;
            if (chunk < 1024) {
                int row = chunk >> 3, c = chunk & 7;
                uint32_t off = (uint32_t)(row * 128 + c * 16);
                soff[i] = off ^ ((off >> 3) & 0x70);
                grow_[i] = row; gcol[i] = c; isA[i] = true;
            } else {
                int idx = chunk - 1024;
                int b = idx >> 3, c = idx & 7;
                int h = b >> 7, l = b & 127;
                uint32_t off = (uint32_t)(l * 128 + c * 16);
                soff[i] = (uint32_t)(TILE_A + h * 16384) + (off ^ ((off >> 3) & 0x70));
                grow_[i] = h * 256 + (int)rank * 128 + l;   // + t*512 at runtime
                gcol[i] = c; isA[i] = false;
            }
        }
        int es = 0; uint32_t ep = 1;
        for (int t = 0; t < TPP; t++) {
            const int n0 = t * 512;
            for (int kt = 0; kt < KT; kt++) {
                wait_parity(sb + SM_EMPTY + es * 8, ep);
                const uint32_t sbase = sb + SM_OPS + es * STAGE_B;
                const int kb = kt * BK;
#pragma unroll
                for (int i = 0; i < 24; i++) {
                    const __half* src = isA[i]
                        ? A  + (size_t)(m0 + grow_[i]) * K + kb + gcol[i] * 8
                        : Bm + (size_t)(n0 + grow_[i]) * K + kb + gcol[i] * 8;
                    cp16(sbase + soff[i], src);
                }
                cp_arrive_noinc(sb + SM_FLOC + es * 8);
                if (++es == NSTAGE) { es = 0; ep ^= 1; }
            }
        }
    } else if (wid == 8) {
        // ======== MMA issuer / notifier ========
        if (elect_one()) {
            int ls = 0; uint32_t lp = 0;
            int fs = 0; uint32_t fp = 0;
            uint32_t efp = 1;
            for (int t = 0; t < TPP; t++) {
                for (int kt = 0; kt < KT; kt++) {
                    wait_parity(sb + SM_FLOC + ls * 8, lp);
                    fence_proxy_async_cta();
                    mbar_arrive_cluster(sb + SM_FULL + ls * 8, 0);
                    if (rank == 0) {
                        if (kt == 0) {                    // D drained?
                            wait_parity(sb + SM_EPIF, efp);
                            efp ^= 1;
                        }
                        wait_parity(sb + SM_FULL + fs * 8, fp);
                        fence_after_sync();
                        const uint32_t st = sb + SM_OPS + fs * STAGE_B;
                        const uint64_t ad = DESC_BASE | (((st) >> 4) & 0x3FFF);
#pragma unroll
                        for (int h = 0; h < 2; h++) {
                            const uint64_t bd = DESC_BASE |
                                (((st + TILE_A + h * 16384) >> 4) & 0x3FFF);
#pragma unroll
                            for (int ks = 0; ks < 4; ks++)
                                mma_cg2_f16(tmem + h * 256, ad + ks * 2, bd + ks * 2,
                                            IDESC_F16, (kt > 0 || ks > 0) ? 1u : 0u);
                        }
                        commit_mc(sb + SM_EMPTY + fs * 8);
                        if (kt == KT - 1)
                            commit_mc(sb + SM_DONE);
                        if (++fs == NSTAGE) { fs = 0; fp ^= 1; }
                    }
                    if (++ls == NSTAGE) { ls = 0; lp ^= 1; }
                }
            }
        }
    } else {
        // ======== epilogue: warps 4-7, 512 cols, one subpartition each ========
        const int sub  = wid - 4;
        const int lane = tid & 31;
        const int grow = m0 + sub * 32 + lane;
        uint32_t dnp = 0;
        for (int t = 0; t < TPP; t++) {
            wait_parity(sb + SM_DONE, dnp);
            dnp ^= 1;
            fence_after_sync();
#pragma unroll
            for (int c4 = 0; c4 < 16; c4++) {
                uint32_t r[32];
                LDTM_X32(r, tmem + c4 * 32);
                wait_ld();
                const int gc0 = t * 512 + c4 * 32;
#pragma unroll
                for (int j = 0; j < 32; j += 4) {
                    float4 bv = *(const float4*)(bias + gc0 + j);
                    float v0 = __uint_as_float(r[j])     + bv.x;
                    float v1 = __uint_as_float(r[j + 1]) + bv.y;
                    float v2 = __uint_as_float(r[j + 2]) + bv.z;
                    float v3 = __uint_as_float(r[j + 3]) + bv.w;
                    if (RELU) {
                        __half2 h01 = __floats2half2_rn(fmaxf(v0, 0.f), fmaxf(v1, 0.f));
                        __half2 h23 = __floats2half2_rn(fmaxf(v2, 0.f), fmaxf(v3, 0.f));
                        st_cs_h4((__half*)Cv + (size_t)grow * N + gc0 + j,
                                 *(uint32_t*)&h01, *(uint32_t*)&h23);
                    } else {
                        st_cs4((float*)Cv + (size_t)grow * N + gc0 + j, v0, v1, v2, v3);
                    }
                }
            }
            fence_before_sync();
            mbar_arrive_cluster(sb + SM_EPIF, 0);
        }
    }

    __syncthreads();
    if (wid == 8) tmem_dealloc_cg2(tmem, 512);
    cluster_sync();
#else
    // ================= fallback: legacy mma.sync fp16 (generic PTX pass) ========
    // 256-wide tiles, 2*TPP of them. A 128x64 halves (stride 72), B 256x64.
    extern __shared__ __half smh[];
    const int tid  = threadIdx.x;
    const int lane = tid & 31;
    const int wid  = tid >> 5;
    const int m0 = blockIdx.y * 256 + blockIdx.x * 128;
    const int KT2 = K / 64;
    const int AT = 128 * 72;
    const int BT = 256 * 72;
    const uint32_t s0 = smem_u32(smh);

    for (int t = 0; t < 2 * TPP; t++) {
        const int nb = t * 256;
        float acc[4][8][4];
        if (tid < 256) {
#pragma unroll
            for (int i = 0; i < 4; i++)
#pragma unroll
                for (int j = 0; j < 8; j++)
#pragma unroll
                    for (int c = 0; c < 4; c++) acc[i][j][c] = 0.f;
        }
        auto load_tile = [&](int kt, int st) {
            if (tid < 256) {
                const __half* Ag = A  + (size_t)m0 * K + (size_t)kt * 64;
                const __half* Bg = Bm + (size_t)nb * K + (size_t)kt * 64;
                const uint32_t sA = s0 + (uint32_t)(st * (AT + BT)) * 2;
                const uint32_t sB = sA + (uint32_t)AT * 2;
#pragma unroll
                for (int q = 0; q < 4; q++) {
                    int ch = tid + q * 256; int row = ch >> 3, c8 = ch & 7;
                    cp16(sA + (uint32_t)(row * 72 + c8 * 8) * 2, Ag + (size_t)row * K + c8 * 8);
                }
#pragma unroll
                for (int q = 0; q < 8; q++) {
                    int ch = tid + q * 256; int row = ch >> 3, c8 = ch & 7;
                    cp16(sB + (uint32_t)(row * 72 + c8 * 8) * 2, Bg + (size_t)row * K + c8 * 8);
                }
            }
            asm volatile("cp.async.commit_group;");
        };
        load_tile(0, 0);
        for (int kt = 0; kt < KT2; kt++) {
            const int st = kt & 1;
            if (kt + 1 < KT2) { load_tile(kt + 1, st ^ 1);
                                asm volatile("cp.async.wait_group 1;"); }
            else              { asm volatile("cp.async.wait_group 0;"); }
            __syncthreads();
            if (tid < 256) {
                const __half* As = smh + st * (AT + BT);
                const __half* Bs = As + AT;
                const int wm = wid >> 2, wn = wid & 3;
                const int g = lane >> 2, tg = lane & 3;
#pragma unroll
                for (int ks = 0; ks < 4; ks++) {
                    const int k0 = ks * 16;
                    uint32_t af[4][4], bf[8][2];
#pragma unroll
                    for (int i = 0; i < 4; i++) {
                        const int r = wm * 64 + i * 16 + g;
                        af[i][0] = *(const uint32_t*)(As + (r    ) * 72 + k0 + 2 * tg);
                        af[i][1] = *(const uint32_t*)(As + (r + 8) * 72 + k0 + 2 * tg);
                        af[i][2] = *(const uint32_t*)(As + (r    ) * 72 + k0 + 2 * tg + 8);
                        af[i][3] = *(const uint32_t*)(As + (r + 8) * 72 + k0 + 2 * tg + 8);
                    }
#pragma unroll
                    for (int j = 0; j < 8; j++) {
                        const int c = wn * 64 + j * 8 + g;
                        bf[j][0] = *(const uint32_t*)(Bs + c * 72 + k0 + 2 * tg);
                        bf[j][1] = *(const uint32_t*)(Bs + c * 72 + k0 + 2 * tg + 8);
                    }
#pragma unroll
                    for (int i = 0; i < 4; i++)
#pragma unroll
                        for (int j = 0; j < 8; j++)
                            mma_f16(acc[i][j], af[i], bf[j]);
                }
            }
            __syncthreads();
        }
        if (tid < 256) {
            const int wm = wid >> 2, wn = wid & 3;
            const int g = lane >> 2, tg = lane & 3;
#pragma unroll
            for (int i = 0; i < 4; i++) {
                const int r0 = m0 + wm * 64 + i * 16 + g;
#pragma unroll
                for (int j = 0; j < 8; j++) {
                    const int c = nb + wn * 64 + j * 8 + tg * 2;
                    const float bv0 = bias[c], bv1 = bias[c + 1];
                    float v0 = acc[i][j][0] + bv0, v1 = acc[i][j][1] + bv1;
                    float v2 = acc[i][j][2] + bv0, v3 = acc[i][j][3] + bv1;
                    if (RELU) {
                        __half2 hA = __floats2half2_rn(fmaxf(v0, 0.f), fmaxf(v1, 0.f));
                        __half2 hB = __floats2half2_rn(fmaxf(v2, 0.f), fmaxf(v3, 0.f));
                        *(__half2*)((__half*)Cv + (size_t)r0 * N + c)       = hA;
                        *(__half2*)((__half*)Cv + (size_t)(r0 + 8) * N + c) = hB;
                    } else {
                        *(float2*)((float*)Cv + (size_t)r0 * N + c)       = make_float2(v0, v1);
                        *(float2*)((float*)Cv + (size_t)(r0 + 8) * N + c) = make_float2(v2, v3);
                    }
                }
            }
        }
        __syncthreads();
    }
#endif
}

// ---------------- launch ----------------
extern "C" void kernel_launch(void* const* d_in, const int* in_sizes, int n_in,
                              void* d_out, int out_size) {
    (void)in_sizes; (void)n_in; (void)out_size;
    const float* x  = (const float*)d_in[0];
    const float* W1 = (const float*)d_in[1];
    const float* b1 = (const float*)d_in[2];
    const float* W2 = (const float*)d_in[3];
    const float* b2 = (const float*)d_in[4];
    float* out = (float*)d_out;

    __half *inter, *xh, *w1h, *w2h;
    cudaGetSymbolAddress((void**)&inter, g_inter);
    cudaGetSymbolAddress((void**)&xh,  g_xh);
    cudaGetSymbolAddress((void**)&w1h, g_w1h);
    cudaGetSymbolAddress((void**)&w2h, g_w2h);

    cudaFuncSetAttribute(ffn_gemm<true>,
                         cudaFuncAttributeMaxDynamicSharedMemorySize, SMEM_TOTAL);
    cudaFuncSetAttribute(ffn_gemm<false>,
                         cudaFuncAttributeMaxDynamicSharedMemorySize, SMEM_TOTAL);

    // Prepass: f32 -> f16 (rn) of X, W1, W2.
    {
        int n8;
        n8 = MTOT * HID / 8;
        cvt_f16_kernel<<<(n8 + 255) / 256, 256>>>((const float4*)x,  (uint4*)xh,  n8);
        n8 = ITR * HID / 8;
        cvt_f16_kernel<<<(n8 + 255) / 256, 256>>>((const float4*)W1, (uint4*)w1h, n8);
        n8 = HID * ITR / 8;
        cvt_f16_kernel<<<(n8 + 255) / 256, 256>>>((const float4*)W2, (uint4*)w2h, n8);
    }

    // GEMM1: inter(f16) = ReLU(X @ W1^T + b1)  [16384,4096], K=1024, 8 tiles of 512
    ffn_gemm<true><<<dim3(2, MTOT / 256, 1), 288, SMEM_TOTAL>>>(
        xh, w1h, b1, inter, HID, ITR, ITR / 512);

    // GEMM2: out(f32) = inter @ W2^T + b2      [16384,1024], K=4096, 2 tiles of 512
    ffn_gemm<false><<<dim3(2, MTOT / 256, 1), 288, SMEM_TOTAL>>>(
        inter, w2h, b2, out, ITR, HID, HID / 512);
}